// round 1
// baseline (speedup 1.0000x reference)
#include <cuda_runtime.h>

#define BATCH 16
#define CHN   64
#define HW    65536
#define HW4   (HW / 4)

// Per-(batch, pooled-channel) statistics. Zeroed every launch by zero_stats_k.
__device__ float g_sum[BATCH][3];
__device__ float g_sumsq[BATCH][3];
__device__ float g_cnt[BATCH];

__global__ void zero_stats_k() {
    int i = threadIdx.x;
    if (i < BATCH * 3) {
        (&g_sum[0][0])[i]   = 0.f;
        (&g_sumsq[0][0])[i] = 0.f;
    }
    if (i < BATCH) g_cnt[i] = 0.f;
}

__device__ __forceinline__ float warp_sum(float v) {
#pragma unroll
    for (int o = 16; o; o >>= 1) v += __shfl_xor_sync(0xffffffffu, v, o);
    return v;
}

// Pass 1: channel pool (max/mean/min over C=64) + masked partial sums.
// Each thread owns 4 consecutive pixels (float4). xc written to `out`.
__global__ void __launch_bounds__(256) pool_stats_k(
    const float* __restrict__ x,
    const int*   __restrict__ mask,
    float*       __restrict__ out)
{
    const int b  = blockIdx.y;
    const int p4 = blockIdx.x * 256 + threadIdx.x;

    const float4* xb = reinterpret_cast<const float4*>(x) + (size_t)b * CHN * HW4 + p4;

    float4 v = xb[0];
    float4 vmax = v, vmin = v, vsum = v;
#pragma unroll
    for (int c = 1; c < CHN; ++c) {
        float4 t = xb[(size_t)c * HW4];
        vmax.x = fmaxf(vmax.x, t.x); vmax.y = fmaxf(vmax.y, t.y);
        vmax.z = fmaxf(vmax.z, t.z); vmax.w = fmaxf(vmax.w, t.w);
        vmin.x = fminf(vmin.x, t.x); vmin.y = fminf(vmin.y, t.y);
        vmin.z = fminf(vmin.z, t.z); vmin.w = fminf(vmin.w, t.w);
        vsum.x += t.x; vsum.y += t.y; vsum.z += t.z; vsum.w += t.w;
    }
    const float inv = 1.f / (float)CHN;
    float4 vmean = make_float4(vsum.x * inv, vsum.y * inv, vsum.z * inv, vsum.w * inv);

    // Write pooled channels (intermediate xc) into d_out.
    float4* ob = reinterpret_cast<float4*>(out) + (size_t)b * 3 * HW4 + p4;
    ob[0]       = vmax;
    ob[HW4]     = vmean;
    ob[2 * HW4] = vmin;

    // Masked partial sums.
    int4 mk = reinterpret_cast<const int4*>(mask)[(size_t)b * HW4 + p4];
    float m0 = (mk.x == 1) ? 1.f : 0.f;
    float m1 = (mk.y == 1) ? 1.f : 0.f;
    float m2 = (mk.z == 1) ? 1.f : 0.f;
    float m3 = (mk.w == 1) ? 1.f : 0.f;

    float vals[7];
    vals[0] = vmax.x  * m0 + vmax.y  * m1 + vmax.z  * m2 + vmax.w  * m3;
    vals[1] = vmax.x * vmax.x * m0 + vmax.y * vmax.y * m1 + vmax.z * vmax.z * m2 + vmax.w * vmax.w * m3;
    vals[2] = vmean.x * m0 + vmean.y * m1 + vmean.z * m2 + vmean.w * m3;
    vals[3] = vmean.x * vmean.x * m0 + vmean.y * vmean.y * m1 + vmean.z * vmean.z * m2 + vmean.w * vmean.w * m3;
    vals[4] = vmin.x  * m0 + vmin.y  * m1 + vmin.z  * m2 + vmin.w  * m3;
    vals[5] = vmin.x * vmin.x * m0 + vmin.y * vmin.y * m1 + vmin.z * vmin.z * m2 + vmin.w * vmin.w * m3;
    vals[6] = m0 + m1 + m2 + m3;

    __shared__ float sh[8][7];
    const int lane = threadIdx.x & 31;
    const int wid  = threadIdx.x >> 5;

#pragma unroll
    for (int i = 0; i < 7; ++i) vals[i] = warp_sum(vals[i]);
    if (lane == 0) {
#pragma unroll
        for (int i = 0; i < 7; ++i) sh[wid][i] = vals[i];
    }
    __syncthreads();
    if (wid == 0) {
#pragma unroll
        for (int i = 0; i < 7; ++i) {
            float t = (lane < 8) ? sh[lane][i] : 0.f;
            t = warp_sum(t);
            if (lane == 0) {
                float* dst;
                if (i == 6)            dst = &g_cnt[b];
                else if (i & 1)        dst = &g_sumsq[b][i >> 1];
                else                   dst = &g_sum[b][i >> 1];
                atomicAdd(dst, t);
            }
        }
    }
}

// Pass 2: normalize xc in place: ((xc - mean) / std) * m, unbiased std.
__global__ void __launch_bounds__(256) norm_k(
    float*     __restrict__ out,
    const int* __restrict__ mask)
{
    const int b  = blockIdx.z;
    const int ch = blockIdx.y;
    const int p4 = blockIdx.x * 256 + threadIdx.x;

    const float cnt  = g_cnt[b];
    const float s    = g_sum[b][ch];
    const float mean = s / cnt;
    const float var  = (g_sumsq[b][ch] - s * mean) / (cnt - 1.f);
    const float rstd = rsqrtf(var);

    float4* o = reinterpret_cast<float4*>(out) + ((size_t)b * 3 + ch) * HW4 + p4;
    float4 v = *o;
    int4 mk = reinterpret_cast<const int4*>(mask)[(size_t)b * HW4 + p4];

    v.x = (mk.x == 1) ? (v.x - mean) * rstd : 0.f;
    v.y = (mk.y == 1) ? (v.y - mean) * rstd : 0.f;
    v.z = (mk.z == 1) ? (v.z - mean) * rstd : 0.f;
    v.w = (mk.w == 1) ? (v.w - mean) * rstd : 0.f;

    *o = v;
}

extern "C" void kernel_launch(void* const* d_in, const int* in_sizes, int n_in,
                              void* d_out, int out_size)
{
    // metadata order: x (16*64*256*256 fp32), mask (16*256*256 int32).
    // Defensive: identify by element count.
    const float* x;
    const int*   mask;
    if (in_sizes[0] > in_sizes[1]) {
        x    = (const float*)d_in[0];
        mask = (const int*)d_in[1];
    } else {
        x    = (const float*)d_in[1];
        mask = (const int*)d_in[0];
    }
    float* out = (float*)d_out;

    zero_stats_k<<<1, 64>>>();

    dim3 g1(HW4 / 256, BATCH);
    pool_stats_k<<<g1, 256>>>(x, mask, out);

    dim3 g2(HW4 / 256, 3, BATCH);
    norm_k<<<g2, 256>>>(out, mask);
}

// round 2
// speedup vs baseline: 1.0054x; 1.0054x over previous
#include <cuda_runtime.h>

#define BATCH 16
#define CHN   64
#define HW    65536
#define HW4   (HW / 4)
#define NBLK  64   // HW4 / 256: pass1 blocks per batch

// Per-(batch, block) partial sums, written fresh every launch (no zeroing,
// no atomics needed): [0]=max_s [1]=max_sq [2]=mean_s [3]=mean_sq
//                     [4]=min_s [5]=min_sq [6]=cnt [7]=pad
__device__ float g_part[BATCH][NBLK][8];

__device__ __forceinline__ float warp_sum(float v) {
#pragma unroll
    for (int o = 16; o; o >>= 1) v += __shfl_xor_sync(0xffffffffu, v, o);
    return v;
}

// Pass 1: channel pool (max/mean/min over C=64) + masked partial sums.
// Each thread owns 4 consecutive pixels (float4). xc written to `out`.
__global__ void __launch_bounds__(256) pool_stats_k(
    const float* __restrict__ x,
    const int*   __restrict__ mask,
    float*       __restrict__ out)
{
    const int b  = blockIdx.y;
    const int p4 = blockIdx.x * 256 + threadIdx.x;

    const float4* xb = reinterpret_cast<const float4*>(x) + (size_t)b * CHN * HW4 + p4;

    float4 v = __ldcs(&xb[0]);  // streaming: evict-first, keep L2 for out/mask
    float4 vmax = v, vmin = v, vsum = v;
#pragma unroll
    for (int c = 1; c < CHN; ++c) {
        float4 t = __ldcs(&xb[(size_t)c * HW4]);
        vmax.x = fmaxf(vmax.x, t.x); vmax.y = fmaxf(vmax.y, t.y);
        vmax.z = fmaxf(vmax.z, t.z); vmax.w = fmaxf(vmax.w, t.w);
        vmin.x = fminf(vmin.x, t.x); vmin.y = fminf(vmin.y, t.y);
        vmin.z = fminf(vmin.z, t.z); vmin.w = fminf(vmin.w, t.w);
        vsum.x += t.x; vsum.y += t.y; vsum.z += t.z; vsum.w += t.w;
    }
    const float inv = 1.f / (float)CHN;
    float4 vmean = make_float4(vsum.x * inv, vsum.y * inv, vsum.z * inv, vsum.w * inv);

    // Write pooled channels (intermediate xc) into d_out.
    float4* ob = reinterpret_cast<float4*>(out) + (size_t)b * 3 * HW4 + p4;
    ob[0]       = vmax;
    ob[HW4]     = vmean;
    ob[2 * HW4] = vmin;

    // Masked partial sums.
    int4 mk = reinterpret_cast<const int4*>(mask)[(size_t)b * HW4 + p4];
    float m0 = (mk.x == 1) ? 1.f : 0.f;
    float m1 = (mk.y == 1) ? 1.f : 0.f;
    float m2 = (mk.z == 1) ? 1.f : 0.f;
    float m3 = (mk.w == 1) ? 1.f : 0.f;

    float vals[7];
    vals[0] = vmax.x  * m0 + vmax.y  * m1 + vmax.z  * m2 + vmax.w  * m3;
    vals[1] = vmax.x * vmax.x * m0 + vmax.y * vmax.y * m1 + vmax.z * vmax.z * m2 + vmax.w * vmax.w * m3;
    vals[2] = vmean.x * m0 + vmean.y * m1 + vmean.z * m2 + vmean.w * m3;
    vals[3] = vmean.x * vmean.x * m0 + vmean.y * vmean.y * m1 + vmean.z * vmean.z * m2 + vmean.w * vmean.w * m3;
    vals[4] = vmin.x  * m0 + vmin.y  * m1 + vmin.z  * m2 + vmin.w  * m3;
    vals[5] = vmin.x * vmin.x * m0 + vmin.y * vmin.y * m1 + vmin.z * vmin.z * m2 + vmin.w * vmin.w * m3;
    vals[6] = m0 + m1 + m2 + m3;

    __shared__ float sh[8][7];
    const int lane = threadIdx.x & 31;
    const int wid  = threadIdx.x >> 5;

#pragma unroll
    for (int i = 0; i < 7; ++i) vals[i] = warp_sum(vals[i]);
    if (lane == 0) {
#pragma unroll
        for (int i = 0; i < 7; ++i) sh[wid][i] = vals[i];
    }
    __syncthreads();
    if (wid == 0) {
#pragma unroll
        for (int i = 0; i < 7; ++i) {
            float t = (lane < 8) ? sh[lane][i] : 0.f;
            t = warp_sum(t);
            if (lane == 0) g_part[b][blockIdx.x][i] = t;
        }
    }
}

// Pass 2: reduce per-block partials (L2-resident, tiny), then normalize all
// 3 pooled channels in place: ((xc - mean) / std) * m, unbiased std.
__global__ void __launch_bounds__(256) norm_k(
    float*     __restrict__ out,
    const int* __restrict__ mask)
{
    const int b   = blockIdx.y;
    const int p4  = blockIdx.x * 256 + threadIdx.x;
    const int tid = threadIdx.x;

    __shared__ float s_mean[3], s_rstd[3];
    __shared__ float s_tmp[2][7];

    // --- stats prologue: reduce 64 partials x 7 values over threads 0..63 ---
    if (tid < 64) {
        const float4* pr = reinterpret_cast<const float4*>(&g_part[b][tid][0]);
        float4 a = pr[0];   // max_s, max_sq, mean_s, mean_sq
        float4 c = pr[1];   // min_s, min_sq, cnt, pad
        float vals[7] = {a.x, a.y, a.z, a.w, c.x, c.y, c.z};
#pragma unroll
        for (int i = 0; i < 7; ++i) vals[i] = warp_sum(vals[i]);
        if ((tid & 31) == 0) {
#pragma unroll
            for (int i = 0; i < 7; ++i) s_tmp[tid >> 5][i] = vals[i];
        }
    }
    __syncthreads();
    if (tid < 3) {
        const float cnt = s_tmp[0][6] + s_tmp[1][6];
        const float s   = s_tmp[0][2 * tid]     + s_tmp[1][2 * tid];
        const float sq  = s_tmp[0][2 * tid + 1] + s_tmp[1][2 * tid + 1];
        const float mean = s / cnt;
        const float var  = (sq - s * mean) / (cnt - 1.f);
        s_mean[tid] = mean;
        s_rstd[tid] = rsqrtf(var);
    }
    __syncthreads();

    // --- normalize: one mask read serves all 3 channels ---
    int4 mk = reinterpret_cast<const int4*>(mask)[(size_t)b * HW4 + p4];
    float4* ob = reinterpret_cast<float4*>(out) + (size_t)b * 3 * HW4 + p4;

#pragma unroll
    for (int ch = 0; ch < 3; ++ch) {
        const float mean = s_mean[ch];
        const float rstd = s_rstd[ch];
        float4 v = ob[(size_t)ch * HW4];
        v.x = (mk.x == 1) ? (v.x - mean) * rstd : 0.f;
        v.y = (mk.y == 1) ? (v.y - mean) * rstd : 0.f;
        v.z = (mk.z == 1) ? (v.z - mean) * rstd : 0.f;
        v.w = (mk.w == 1) ? (v.w - mean) * rstd : 0.f;
        ob[(size_t)ch * HW4] = v;
    }
}

extern "C" void kernel_launch(void* const* d_in, const int* in_sizes, int n_in,
                              void* d_out, int out_size)
{
    const float* x;
    const int*   mask;
    if (in_sizes[0] > in_sizes[1]) {
        x    = (const float*)d_in[0];
        mask = (const int*)d_in[1];
    } else {
        x    = (const float*)d_in[1];
        mask = (const int*)d_in[0];
    }
    float* out = (float*)d_out;

    dim3 g1(NBLK, BATCH);
    pool_stats_k<<<g1, 256>>>(x, mask, out);

    dim3 g2(NBLK, BATCH);
    norm_k<<<g2, 256>>>(out, mask);
}